// round 10
// baseline (speedup 1.0000x reference)
#include <cuda_runtime.h>
#include <math.h>

#define BB   8192
#define INF  512
#define OUTF 1024
#define KWID 1535   // weight row length (IN_F + OUT_F - 1)
#define CB   64
#define NBLK (OUTF / CB)
#define TT   4      // slot-threads per row
#define SL   16     // slots (columns) per thread  (CB/TT)

// Column-major fp32 buffers: [col * BB + row]
__device__ float g_XW[(size_t)BB * OUTF];  // x @ Wx^T + bias (ref chain order)
__device__ float g_D [(size_t)BB * OUTF];  // prefix dot chain (blocks >=2 only)

// ---------------------------------------------------------------------------
// XLA-faithful fp32 logistic: 0.5*fast_tanh(0.5*x) + 0.5 (EmitFastTanh
// rational approx). All mul/add UNFUSED, matching XLA's raw FMul/FAdd.
// ---------------------------------------------------------------------------
__device__ __forceinline__ float xla_fast_tanh(float x)
{
    float ax = fabsf(x);
    float xc = fminf(fmaxf(x, -7.90531110763549805f), 7.90531110763549805f);
    float x2 = __fmul_rn(xc, xc);
    float np = __fadd_rn(__fmul_rn(x2, -2.76076847742355e-16f), 2.00018790482477e-13f);
    np = __fadd_rn(__fmul_rn(x2, np), -8.60467152213735e-11f);
    np = __fadd_rn(__fmul_rn(x2, np),  5.12229709037114e-08f);
    np = __fadd_rn(__fmul_rn(x2, np),  1.48572235717979e-05f);
    np = __fadd_rn(__fmul_rn(x2, np),  6.37261928875436e-04f);
    np = __fadd_rn(__fmul_rn(x2, np),  4.89352455891786e-03f);
    np = __fmul_rn(xc, np);
    float dq = __fadd_rn(__fmul_rn(x2, 1.19825839466702e-06f), 1.18534705686654e-04f);
    dq = __fadd_rn(__fmul_rn(x2, dq), 2.26843463243900e-03f);
    dq = __fadd_rn(__fmul_rn(x2, dq), 4.89352518554385e-03f);
    float r = __fdiv_rn(np, dq);
    return (ax < 0.0004f) ? x : r;
}

__device__ __forceinline__ float xla_logistic_f32(float x)
{
    float t = xla_fast_tanh(__fmul_rn(0.5f, x));
    return __fadd_rn(__fmul_rn(0.5f, t), 0.5f);
}

// ---------------------------------------------------------------------------
// GEMM, double-buffered (UNCHANGED from R9): strict ascending-k FMA chain per
// element (Eigen-exact). 64x64 tile, BK=16, 256 threads, 4x4 microtile.
// mode 0: dst = acc + bias.  mode 1: dst = acc.  mode 2: RMW chain continue.
// ---------------------------------------------------------------------------
__global__ void __launch_bounds__(256)
gemm_kernel(const float* __restrict__ A, const float* __restrict__ W,
            const float* __restrict__ bias, float* __restrict__ dst,
            int K, int nbase0, int koff, int lda, int mode)
{
    __shared__ float As[2][16][68];
    __shared__ float Bs[2][16][68];
    const int tid   = threadIdx.x;
    const int m0    = blockIdx.x * 64;
    const int nbase = nbase0 + blockIdx.y * 64;
    const int tx = tid & 15;
    const int ty = tid >> 4;
    const int am = tid >> 2;
    const int ak = (tid & 3) << 2;
    const int bk = tid & 15;
    const int bn = tid >> 4;

    float acc[4][4];
    if (mode == 2) {
#pragma unroll
        for (int j = 0; j < 4; ++j) {
            int col = nbase + (tx << 2) + j;
            float4 o = *reinterpret_cast<const float4*>(
                dst + (size_t)col * BB + m0 + (ty << 2));
            acc[0][j] = o.x; acc[1][j] = o.y; acc[2][j] = o.z; acc[3][j] = o.w;
        }
    } else {
#pragma unroll
        for (int i = 0; i < 4; ++i)
#pragma unroll
            for (int j = 0; j < 4; ++j) acc[i][j] = 0.0f;
    }

    const float* Arow  = A + (size_t)(m0 + am) * lda + ak;
    const float* Wbase = W + (size_t)koff;

    float4 av = *reinterpret_cast<const float4*>(Arow);
    float  bv[4];
#pragma unroll
    for (int q = 0; q < 4; ++q)
        bv[q] = Wbase[(size_t)(nbase + bn + q * 16) * KWID + bk];

    As[0][ak + 0][am] = av.x;
    As[0][ak + 1][am] = av.y;
    As[0][ak + 2][am] = av.z;
    As[0][ak + 3][am] = av.w;
#pragma unroll
    for (int q = 0; q < 4; ++q) Bs[0][bk][bn + q * 16] = bv[q];
    __syncthreads();

    int cur = 0;
    for (int k0 = 0; k0 < K; k0 += 16) {
        const int has_next = (k0 + 16 < K);
        if (has_next) {
            av = *reinterpret_cast<const float4*>(Arow + k0 + 16);
#pragma unroll
            for (int q = 0; q < 4; ++q)
                bv[q] = Wbase[(size_t)(nbase + bn + q * 16) * KWID + k0 + 16 + bk];
        }
#pragma unroll
        for (int kk = 0; kk < 16; ++kk) {
            float4 a4 = *reinterpret_cast<const float4*>(&As[cur][kk][ty << 2]);
            float4 b4 = *reinterpret_cast<const float4*>(&Bs[cur][kk][tx << 2]);
            float a[4] = {a4.x, a4.y, a4.z, a4.w};
            float b[4] = {b4.x, b4.y, b4.z, b4.w};
#pragma unroll
            for (int i = 0; i < 4; ++i)
#pragma unroll
                for (int j = 0; j < 4; ++j)
                    acc[i][j] = fmaf(a[i], b[j], acc[i][j]);
        }
        if (has_next) {
            const int nxt = cur ^ 1;
            As[nxt][ak + 0][am] = av.x;
            As[nxt][ak + 1][am] = av.y;
            As[nxt][ak + 2][am] = av.z;
            As[nxt][ak + 3][am] = av.w;
#pragma unroll
            for (int q = 0; q < 4; ++q) Bs[nxt][bk][bn + q * 16] = bv[q];
            __syncthreads();
            cur = nxt;
        }
    }

#pragma unroll
    for (int j = 0; j < 4; ++j) {
        int col = nbase + (tx << 2) + j;
        float* d = dst + (size_t)col * BB + m0 + (ty << 2);
        float4 v;
        v.x = acc[0][j]; v.y = acc[1][j]; v.z = acc[2][j]; v.w = acc[3][j];
        if (mode == 0) {
            float bv2 = bias[col];
            v.x = __fadd_rn(v.x, bv2);
            v.y = __fadd_rn(v.y, bv2);
            v.z = __fadd_rn(v.z, bv2);
            v.w = __fadd_rn(v.w, bv2);
        }
        *reinterpret_cast<float4*>(d) = v;
    }
}

// ---------------------------------------------------------------------------
// Fused sweep: appends block (k-1)'s 64 sample terms (j ascending) onto the
// g_D prefix, then runs the intra-block slot-split sweep. Per-column chain:
// g_D (j < 64(k-1), built ascending by serial updR RMW) -> fused terms
// (j in [64(k-1), 64k)) -> intra-block terms. Exactly the reference order.
// smem aliased: bufA = prev samples, then tri; bufB = W slab, then staging.
// ---------------------------------------------------------------------------
__global__ void __launch_bounds__(256)
seq_kernel(int base, const float* __restrict__ W, const float* __restrict__ U,
           float* __restrict__ out, float* __restrict__ Lout)
{
    __shared__ __align__(16) float bufA[CB][CB + 4];
    __shared__ __align__(16) float bufB[CB][CB + 4];
    const int tid  = threadIdx.x;
    const int r0   = blockIdx.x * CB;
    const int rl   = tid >> 2;
    const int t    = tid & 3;
    const int r    = r0 + rl;
    const int lane = tid & 31;

    float ureg[SL], xwreg[SL], accf[SL], logits[SL];
    {
        const float* Urow = U + (size_t)r * OUTF + base + (t << 4);
#pragma unroll
        for (int m = 0; m < SL; m += 4) {
            float4 v = *reinterpret_cast<const float4*>(Urow + m);
            ureg[m] = v.x; ureg[m+1] = v.y; ureg[m+2] = v.z; ureg[m+3] = v.w;
        }
    }
#pragma unroll
    for (int m = 0; m < SL; ++m)
        xwreg[m] = g_XW[(size_t)(base + (t << 4) + m) * BB + r];
    if (base >= 2 * CB) {           // g_D exists only for blocks >= 2
#pragma unroll
        for (int m = 0; m < SL; ++m)
            accf[m] = g_D[(size_t)(base + (t << 4) + m) * BB + r];
    } else {
#pragma unroll
        for (int m = 0; m < SL; ++m) accf[m] = 0.0f;
    }

    if (base > 0) {
        // prev samples (bufA[rr][j]) and fused W slab (bufB[j][c]), coalesced
#pragma unroll 1
        for (int idx = tid; idx < CB * CB; idx += 256) {
            int j = idx & (CB - 1), rr = idx >> 6;
            bufA[rr][j] = out[(size_t)(r0 + rr) * OUTF + (base - CB) + j];
        }
#pragma unroll 1
        for (int idx = tid; idx < CB * CB; idx += 256) {
            int j = idx & (CB - 1), c = idx >> 6;
            bufB[j][c] = W[(size_t)(base + c) * KWID + INF + (base - CB) + j];
        }
        __syncthreads();
        const float* wb = &bufB[0][0] + (t << 4);
#pragma unroll 2
        for (int j = 0; j < CB; ++j) {
            float s = bufA[rl][j];
            const float* wr = wb + j * (CB + 4);
#pragma unroll
            for (int mm = 0; mm < SL; mm += 4) {
                float4 wv = *reinterpret_cast<const float4*>(wr + mm);
                accf[mm + 0] = fmaf(s, wv.x, accf[mm + 0]);
                accf[mm + 1] = fmaf(s, wv.y, accf[mm + 1]);
                accf[mm + 2] = fmaf(s, wv.z, accf[mm + 2]);
                accf[mm + 3] = fmaf(s, wv.w, accf[mm + 3]);
            }
        }
        __syncthreads();
    }

    // intra-block zero-padded triangle into bufA
#pragma unroll 1
    for (int idx = tid; idx < CB * CB; idx += 256) {
        int i = idx & (CB - 1);
        int j = idx >> 6;
        float v = 0.0f;
        if (j > i) v = W[(size_t)(base + j) * KWID + INF + base + i];
        bufA[i][j] = v;
    }
    __syncthreads();

    unsigned smask = 0u;
    const float* tbase = &bufA[0][0] + (t << 4);

#pragma unroll 1
    for (int g = 0; g < TT; ++g) {
        const int src = (lane & ~3) | g;
#pragma unroll
        for (int m = 0; m < SL; ++m) {
            const int i = (g << 4) + m;
            float cand = __fadd_rn(xwreg[m], accf[m]);
            float p    = xla_logistic_f32(cand);
            float sc   = (ureg[m] < p) ? 1.0f : 0.0f;
            float s    = __shfl_sync(0xffffffffu, sc, src);
            if (t == g) {
                logits[m] = cand;
                smask |= (sc != 0.0f ? 1u : 0u) << m;
            }
            const float* trow = tbase + i * (CB + 4);
#pragma unroll
            for (int mm = 0; mm < SL; mm += 4) {
                float4 tv = *reinterpret_cast<const float4*>(trow + mm);
                accf[mm + 0] = fmaf(s, tv.x, accf[mm + 0]);
                accf[mm + 1] = fmaf(s, tv.y, accf[mm + 1]);
                accf[mm + 2] = fmaf(s, tv.z, accf[mm + 2]);
                accf[mm + 3] = fmaf(s, tv.w, accf[mm + 3]);
            }
        }
    }

#pragma unroll
    for (int m = 0; m < SL; m += 4) {
        float4 v; v.x = logits[m]; v.y = logits[m+1]; v.z = logits[m+2]; v.w = logits[m+3];
        *reinterpret_cast<float4*>(&bufB[rl][(t << 4) + m]) = v;
    }
    __syncthreads();
#pragma unroll 1
    for (int idx = tid; idx < CB * CB; idx += 256) {
        int rr = idx >> 6, c = idx & (CB - 1);
        Lout[(size_t)(r0 + rr) * OUTF + base + c] = bufB[rr][c];
    }
    __syncthreads();
#pragma unroll
    for (int m = 0; m < SL; m += 4) {
        float4 v;
        v.x = (float)((smask >> (m + 0)) & 1u);
        v.y = (float)((smask >> (m + 1)) & 1u);
        v.z = (float)((smask >> (m + 2)) & 1u);
        v.w = (float)((smask >> (m + 3)) & 1u);
        *reinterpret_cast<float4*>(&bufB[rl][(t << 4) + m]) = v;
    }
    __syncthreads();
#pragma unroll 1
    for (int idx = tid; idx < CB * CB; idx += 256) {
        int rr = idx >> 6, c = idx & (CB - 1);
        out[(size_t)(r0 + rr) * OUTF + base + c] = bufB[rr][c];
    }
}

// ---------------------------------------------------------------------------
// DAG:
//  sp (HIGH prio): xw0 -> sweep0 -> sweep1(fused) -> ... -> sweep15
//  s2 (low): xw blocks 1..15 in 4 fat groups (grid up to 512).
//  s1 (low): updR(m) after sweep(m): blocks m+2..15 += block-m samples
//            (serial s1 => ascending sample-block order per column).
//  sweep(k) waits eXwG[(k-1)/4] and (k>=2) eUpdR[k-2].
// ---------------------------------------------------------------------------
extern "C" void kernel_launch(void* const* d_in, const int* in_sizes, int n_in,
                              void* d_out, int out_size)
{
    const float* x    = (const float*)d_in[0];
    const float* w    = (const float*)d_in[1];
    const float* bias = (const float*)d_in[2];
    const float* u    = (const float*)d_in[3];
    float* out  = (float*)d_out;
    float* Lout = out + (size_t)BB * OUTF;

    float* xw_ptr;  cudaGetSymbolAddress((void**)&xw_ptr, g_XW);
    float* d_ptr;   cudaGetSymbolAddress((void**)&d_ptr,  g_D);

    int loP, hiP;
    cudaDeviceGetStreamPriorityRange(&loP, &hiP);
    cudaStream_t sp, s1, s2;
    cudaStreamCreateWithPriority(&sp, cudaStreamNonBlocking, hiP);
    cudaStreamCreateWithPriority(&s1, cudaStreamNonBlocking, loP);
    cudaStreamCreateWithPriority(&s2, cudaStreamNonBlocking, loP);

    cudaEvent_t eRoot, eDone, eXwG[4], eSweep[NBLK], eUpdR[NBLK];
    cudaEventCreateWithFlags(&eRoot, cudaEventDisableTiming);
    cudaEventCreateWithFlags(&eDone, cudaEventDisableTiming);
    for (int i = 0; i < 4; ++i) cudaEventCreateWithFlags(&eXwG[i], cudaEventDisableTiming);
    for (int i = 0; i < NBLK; ++i) {
        cudaEventCreateWithFlags(&eSweep[i], cudaEventDisableTiming);
        cudaEventCreateWithFlags(&eUpdR[i],  cudaEventDisableTiming);
    }

    cudaEventRecord(eRoot, 0);
    cudaStreamWaitEvent(sp, eRoot, 0);
    cudaStreamWaitEvent(s1, eRoot, 0);
    cudaStreamWaitEvent(s2, eRoot, 0);

    // s2: xw blocks 1..15 in 4 groups
    for (int g = 0; g < 4; ++g) {
        int b0  = 1 + 4 * g;
        int cnt = (g == 3) ? 3 : 4;
        gemm_kernel<<<dim3(128, cnt), 256, 0, s2>>>(x, w, bias, xw_ptr,
                                                    INF, 64 * b0, 0, INF, 0);
        cudaEventRecord(eXwG[g], s2);
    }

    // sp: xw block 0 + sweep 0
    gemm_kernel<<<dim3(128, 1), 256, 0, sp>>>(x, w, bias, xw_ptr,
                                              INF, 0, 0, INF, 0);
    seq_kernel<<<128, 256, 0, sp>>>(0, w, u, out, Lout);
    cudaEventRecord(eSweep[0], sp);

    for (int k = 1; k < NBLK; ++k) {
        int m = k - 1;
        if (m <= NBLK - 3) {    // updR(m): blocks m+2..15
            cudaStreamWaitEvent(s1, eSweep[m], 0);
            gemm_kernel<<<dim3(128, NBLK - 2 - m), 256, 0, s1>>>(
                out + 64 * m, w, bias, d_ptr,
                64, 64 * (m + 2), INF + 64 * m, OUTF, (m == 0) ? 1 : 2);
            cudaEventRecord(eUpdR[m], s1);
        }
        cudaStreamWaitEvent(sp, eXwG[(k - 1) >> 2], 0);
        if (k >= 2) cudaStreamWaitEvent(sp, eUpdR[k - 2], 0);
        seq_kernel<<<128, 256, 0, sp>>>(64 * k, w, u, out, Lout);
        if (k < NBLK - 1) cudaEventRecord(eSweep[k], sp);
    }

    cudaEventRecord(eDone, sp);
    cudaStreamWaitEvent(0, eDone, 0);

    for (int i = 0; i < 4; ++i) cudaEventDestroy(eXwG[i]);
    for (int i = 0; i < NBLK; ++i) {
        cudaEventDestroy(eSweep[i]);
        cudaEventDestroy(eUpdR[i]);
    }
    cudaEventDestroy(eRoot);
    cudaEventDestroy(eDone);
    cudaStreamDestroy(sp);
    cudaStreamDestroy(s1);
    cudaStreamDestroy(s2);
}

// round 13
// speedup vs baseline: 1.5801x; 1.5801x over previous
#include <cuda_runtime.h>
#include <math.h>

#define BB   8192
#define INF  512
#define OUTF 1024
#define KWID 1535   // weight row length (IN_F + OUT_F - 1)
#define CB   64
#define NBLK (OUTF / CB)
#define TT   4      // slot-threads per row
#define SL   16     // slots (columns) per thread  (CB/TT)

// Column-major fp32 buffers: [col * BB + row]
__device__ float g_XW[(size_t)BB * OUTF];  // x @ Wx^T + bias (ref chain order)
__device__ float g_D [(size_t)BB * OUTF];  // prefix dot chain (blocks >=2 only)

// ---------------------------------------------------------------------------
// XLA-faithful fp32 logistic: 0.5*fast_tanh(0.5*x) + 0.5 (EmitFastTanh
// rational approx). All mul/add UNFUSED, matching XLA's raw FMul/FAdd.
// ---------------------------------------------------------------------------
__device__ __forceinline__ float xla_fast_tanh(float x)
{
    float ax = fabsf(x);
    float xc = fminf(fmaxf(x, -7.90531110763549805f), 7.90531110763549805f);
    float x2 = __fmul_rn(xc, xc);
    float np = __fadd_rn(__fmul_rn(x2, -2.76076847742355e-16f), 2.00018790482477e-13f);
    np = __fadd_rn(__fmul_rn(x2, np), -8.60467152213735e-11f);
    np = __fadd_rn(__fmul_rn(x2, np),  5.12229709037114e-08f);
    np = __fadd_rn(__fmul_rn(x2, np),  1.48572235717979e-05f);
    np = __fadd_rn(__fmul_rn(x2, np),  6.37261928875436e-04f);
    np = __fadd_rn(__fmul_rn(x2, np),  4.89352455891786e-03f);
    np = __fmul_rn(xc, np);
    float dq = __fadd_rn(__fmul_rn(x2, 1.19825839466702e-06f), 1.18534705686654e-04f);
    dq = __fadd_rn(__fmul_rn(x2, dq), 2.26843463243900e-03f);
    dq = __fadd_rn(__fmul_rn(x2, dq), 4.89352518554385e-03f);
    float r = __fdiv_rn(np, dq);
    return (ax < 0.0004f) ? x : r;
}

__device__ __forceinline__ float xla_logistic_f32(float x)
{
    float t = xla_fast_tanh(__fmul_rn(0.5f, x));
    return __fadd_rn(__fmul_rn(0.5f, t), 0.5f);
}

// ---------------------------------------------------------------------------
// GEMM, double-buffered (UNCHANGED from R9): strict ascending-k FMA chain per
// element (Eigen-exact). 64x64 tile, BK=16, 256 threads, 4x4 microtile.
// mode 0: dst = acc + bias.  mode 1: dst = acc.  mode 2: RMW chain continue.
// ---------------------------------------------------------------------------
__global__ void __launch_bounds__(256)
gemm_kernel(const float* __restrict__ A, const float* __restrict__ W,
            const float* __restrict__ bias, float* __restrict__ dst,
            int K, int nbase0, int koff, int lda, int mode)
{
    __shared__ float As[2][16][68];
    __shared__ float Bs[2][16][68];
    const int tid   = threadIdx.x;
    const int m0    = blockIdx.x * 64;
    const int nbase = nbase0 + blockIdx.y * 64;
    const int tx = tid & 15;
    const int ty = tid >> 4;
    const int am = tid >> 2;
    const int ak = (tid & 3) << 2;
    const int bk = tid & 15;
    const int bn = tid >> 4;

    float acc[4][4];
    if (mode == 2) {
#pragma unroll
        for (int j = 0; j < 4; ++j) {
            int col = nbase + (tx << 2) + j;
            float4 o = *reinterpret_cast<const float4*>(
                dst + (size_t)col * BB + m0 + (ty << 2));
            acc[0][j] = o.x; acc[1][j] = o.y; acc[2][j] = o.z; acc[3][j] = o.w;
        }
    } else {
#pragma unroll
        for (int i = 0; i < 4; ++i)
#pragma unroll
            for (int j = 0; j < 4; ++j) acc[i][j] = 0.0f;
    }

    const float* Arow  = A + (size_t)(m0 + am) * lda + ak;
    const float* Wbase = W + (size_t)koff;

    float4 av = *reinterpret_cast<const float4*>(Arow);
    float  bv[4];
#pragma unroll
    for (int q = 0; q < 4; ++q)
        bv[q] = Wbase[(size_t)(nbase + bn + q * 16) * KWID + bk];

    As[0][ak + 0][am] = av.x;
    As[0][ak + 1][am] = av.y;
    As[0][ak + 2][am] = av.z;
    As[0][ak + 3][am] = av.w;
#pragma unroll
    for (int q = 0; q < 4; ++q) Bs[0][bk][bn + q * 16] = bv[q];
    __syncthreads();

    int cur = 0;
    for (int k0 = 0; k0 < K; k0 += 16) {
        const int has_next = (k0 + 16 < K);
        if (has_next) {
            av = *reinterpret_cast<const float4*>(Arow + k0 + 16);
#pragma unroll
            for (int q = 0; q < 4; ++q)
                bv[q] = Wbase[(size_t)(nbase + bn + q * 16) * KWID + k0 + 16 + bk];
        }
#pragma unroll
        for (int kk = 0; kk < 16; ++kk) {
            float4 a4 = *reinterpret_cast<const float4*>(&As[cur][kk][ty << 2]);
            float4 b4 = *reinterpret_cast<const float4*>(&Bs[cur][kk][tx << 2]);
            float a[4] = {a4.x, a4.y, a4.z, a4.w};
            float b[4] = {b4.x, b4.y, b4.z, b4.w};
#pragma unroll
            for (int i = 0; i < 4; ++i)
#pragma unroll
                for (int j = 0; j < 4; ++j)
                    acc[i][j] = fmaf(a[i], b[j], acc[i][j]);
        }
        if (has_next) {
            const int nxt = cur ^ 1;
            As[nxt][ak + 0][am] = av.x;
            As[nxt][ak + 1][am] = av.y;
            As[nxt][ak + 2][am] = av.z;
            As[nxt][ak + 3][am] = av.w;
#pragma unroll
            for (int q = 0; q < 4; ++q) Bs[nxt][bk][bn + q * 16] = bv[q];
            __syncthreads();
            cur = nxt;
        }
    }

#pragma unroll
    for (int j = 0; j < 4; ++j) {
        int col = nbase + (tx << 2) + j;
        float* d = dst + (size_t)col * BB + m0 + (ty << 2);
        float4 v;
        v.x = acc[0][j]; v.y = acc[1][j]; v.z = acc[2][j]; v.w = acc[3][j];
        if (mode == 0) {
            float bv2 = bias[col];
            v.x = __fadd_rn(v.x, bv2);
            v.y = __fadd_rn(v.y, bv2);
            v.z = __fadd_rn(v.z, bv2);
            v.w = __fadd_rn(v.w, bv2);
        }
        *reinterpret_cast<float4*>(d) = v;
    }
}

// ---------------------------------------------------------------------------
// Fused sweep (UNCHANGED from R10): appends block (k-1)'s 64 sample terms
// (j ascending) onto the g_D prefix, then runs the intra-block slot-split
// sweep. Per-column chain: g_D (ascending updR blocks) -> fused terms ->
// intra-block triangle. Exactly the reference order.
// ---------------------------------------------------------------------------
__global__ void __launch_bounds__(256)
seq_kernel(int base, const float* __restrict__ W, const float* __restrict__ U,
           float* __restrict__ out, float* __restrict__ Lout)
{
    __shared__ __align__(16) float bufA[CB][CB + 4];
    __shared__ __align__(16) float bufB[CB][CB + 4];
    const int tid  = threadIdx.x;
    const int r0   = blockIdx.x * CB;
    const int rl   = tid >> 2;
    const int t    = tid & 3;
    const int r    = r0 + rl;
    const int lane = tid & 31;

    float ureg[SL], xwreg[SL], accf[SL], logits[SL];
    {
        const float* Urow = U + (size_t)r * OUTF + base + (t << 4);
#pragma unroll
        for (int m = 0; m < SL; m += 4) {
            float4 v = *reinterpret_cast<const float4*>(Urow + m);
            ureg[m] = v.x; ureg[m+1] = v.y; ureg[m+2] = v.z; ureg[m+3] = v.w;
        }
    }
#pragma unroll
    for (int m = 0; m < SL; ++m)
        xwreg[m] = g_XW[(size_t)(base + (t << 4) + m) * BB + r];
    if (base >= 2 * CB) {           // g_D exists only for blocks >= 2
#pragma unroll
        for (int m = 0; m < SL; ++m)
            accf[m] = g_D[(size_t)(base + (t << 4) + m) * BB + r];
    } else {
#pragma unroll
        for (int m = 0; m < SL; ++m) accf[m] = 0.0f;
    }

    if (base > 0) {
        // prev samples (bufA[rr][j]) and fused W slab (bufB[j][c]), coalesced
#pragma unroll 1
        for (int idx = tid; idx < CB * CB; idx += 256) {
            int j = idx & (CB - 1), rr = idx >> 6;
            bufA[rr][j] = out[(size_t)(r0 + rr) * OUTF + (base - CB) + j];
        }
#pragma unroll 1
        for (int idx = tid; idx < CB * CB; idx += 256) {
            int j = idx & (CB - 1), c = idx >> 6;
            bufB[j][c] = W[(size_t)(base + c) * KWID + INF + (base - CB) + j];
        }
        __syncthreads();
        const float* wb = &bufB[0][0] + (t << 4);
#pragma unroll 2
        for (int j = 0; j < CB; ++j) {
            float s = bufA[rl][j];
            const float* wr = wb + j * (CB + 4);
#pragma unroll
            for (int mm = 0; mm < SL; mm += 4) {
                float4 wv = *reinterpret_cast<const float4*>(wr + mm);
                accf[mm + 0] = fmaf(s, wv.x, accf[mm + 0]);
                accf[mm + 1] = fmaf(s, wv.y, accf[mm + 1]);
                accf[mm + 2] = fmaf(s, wv.z, accf[mm + 2]);
                accf[mm + 3] = fmaf(s, wv.w, accf[mm + 3]);
            }
        }
        __syncthreads();
    }

    // intra-block zero-padded triangle into bufA
#pragma unroll 1
    for (int idx = tid; idx < CB * CB; idx += 256) {
        int i = idx & (CB - 1);
        int j = idx >> 6;
        float v = 0.0f;
        if (j > i) v = W[(size_t)(base + j) * KWID + INF + base + i];
        bufA[i][j] = v;
    }
    __syncthreads();

    unsigned smask = 0u;
    const float* tbase = &bufA[0][0] + (t << 4);

#pragma unroll 1
    for (int g = 0; g < TT; ++g) {
        const int src = (lane & ~3) | g;
#pragma unroll
        for (int m = 0; m < SL; ++m) {
            const int i = (g << 4) + m;
            float cand = __fadd_rn(xwreg[m], accf[m]);
            float p    = xla_logistic_f32(cand);
            float sc   = (ureg[m] < p) ? 1.0f : 0.0f;
            float s    = __shfl_sync(0xffffffffu, sc, src);
            if (t == g) {
                logits[m] = cand;
                smask |= (sc != 0.0f ? 1u : 0u) << m;
            }
            const float* trow = tbase + i * (CB + 4);
#pragma unroll
            for (int mm = 0; mm < SL; mm += 4) {
                float4 tv = *reinterpret_cast<const float4*>(trow + mm);
                accf[mm + 0] = fmaf(s, tv.x, accf[mm + 0]);
                accf[mm + 1] = fmaf(s, tv.y, accf[mm + 1]);
                accf[mm + 2] = fmaf(s, tv.z, accf[mm + 2]);
                accf[mm + 3] = fmaf(s, tv.w, accf[mm + 3]);
            }
        }
    }

#pragma unroll
    for (int m = 0; m < SL; m += 4) {
        float4 v; v.x = logits[m]; v.y = logits[m+1]; v.z = logits[m+2]; v.w = logits[m+3];
        *reinterpret_cast<float4*>(&bufB[rl][(t << 4) + m]) = v;
    }
    __syncthreads();
#pragma unroll 1
    for (int idx = tid; idx < CB * CB; idx += 256) {
        int rr = idx >> 6, c = idx & (CB - 1);
        Lout[(size_t)(r0 + rr) * OUTF + base + c] = bufB[rr][c];
    }
    __syncthreads();
#pragma unroll
    for (int m = 0; m < SL; m += 4) {
        float4 v;
        v.x = (float)((smask >> (m + 0)) & 1u);
        v.y = (float)((smask >> (m + 1)) & 1u);
        v.z = (float)((smask >> (m + 2)) & 1u);
        v.w = (float)((smask >> (m + 3)) & 1u);
        *reinterpret_cast<float4*>(&bufB[rl][(t << 4) + m]) = v;
    }
    __syncthreads();
#pragma unroll 1
    for (int idx = tid; idx < CB * CB; idx += 256) {
        int rr = idx >> 6, c = idx & (CB - 1);
        out[(size_t)(r0 + rr) * OUTF + base + c] = bufB[rr][c];
    }
}

// xw group index containing block k (groups: {1,2},{3-6},{7-10},{11-15})
static inline int xw_group_of(int k)
{
    if (k <= 2)  return 0;
    if (k <= 6)  return 1;
    if (k <= 10) return 2;
    return 3;
}

// ---------------------------------------------------------------------------
// DAG (NO priorities — all streams default):
//  s0 (legacy): xw0 -> sweep0 -> sweep1(fused) -> ... -> sweep15
//  s2: xw blocks 1..15 in 4 groups: {1,2},{3-6},{7-10},{11-15}.
//  s1: updR(m) after sweep(m): blocks m+2..15 += block-m samples
//      (serial s1 => ascending sample-block order per column).
//  sweep(k) waits eXwG[group(k)] and (k>=2) eUpdR[k-2].
// ---------------------------------------------------------------------------
extern "C" void kernel_launch(void* const* d_in, const int* in_sizes, int n_in,
                              void* d_out, int out_size)
{
    const float* x    = (const float*)d_in[0];
    const float* w    = (const float*)d_in[1];
    const float* bias = (const float*)d_in[2];
    const float* u    = (const float*)d_in[3];
    float* out  = (float*)d_out;
    float* Lout = out + (size_t)BB * OUTF;

    float* xw_ptr;  cudaGetSymbolAddress((void**)&xw_ptr, g_XW);
    float* d_ptr;   cudaGetSymbolAddress((void**)&d_ptr,  g_D);

    cudaStream_t s1, s2;
    cudaStreamCreateWithFlags(&s1, cudaStreamNonBlocking);
    cudaStreamCreateWithFlags(&s2, cudaStreamNonBlocking);

    cudaEvent_t eRoot, eXwG[4], eSweep[NBLK], eUpdR[NBLK];
    cudaEventCreateWithFlags(&eRoot, cudaEventDisableTiming);
    for (int i = 0; i < 4; ++i) cudaEventCreateWithFlags(&eXwG[i], cudaEventDisableTiming);
    for (int i = 0; i < NBLK; ++i) {
        cudaEventCreateWithFlags(&eSweep[i], cudaEventDisableTiming);
        cudaEventCreateWithFlags(&eUpdR[i],  cudaEventDisableTiming);
    }

    cudaEventRecord(eRoot, 0);
    cudaStreamWaitEvent(s1, eRoot, 0);
    cudaStreamWaitEvent(s2, eRoot, 0);

    // s2: xw blocks 1..15 in 4 groups
    {
        const int gb0[4] = {1, 3, 7, 11};
        const int gcnt[4] = {2, 4, 4, 5};
        for (int g = 0; g < 4; ++g) {
            gemm_kernel<<<dim3(128, gcnt[g]), 256, 0, s2>>>(
                x, w, bias, xw_ptr, INF, 64 * gb0[g], 0, INF, 0);
            cudaEventRecord(eXwG[g], s2);
        }
    }

    // s0: xw block 0 + sweep 0
    gemm_kernel<<<dim3(128, 1), 256>>>(x, w, bias, xw_ptr, INF, 0, 0, INF, 0);
    seq_kernel<<<128, 256>>>(0, w, u, out, Lout);
    cudaEventRecord(eSweep[0], 0);

    for (int k = 1; k < NBLK; ++k) {
        int m = k - 1;
        if (m <= NBLK - 3) {    // updR(m): blocks m+2..15
            cudaStreamWaitEvent(s1, eSweep[m], 0);
            gemm_kernel<<<dim3(128, NBLK - 2 - m), 256, 0, s1>>>(
                out + 64 * m, w, bias, d_ptr,
                64, 64 * (m + 2), INF + 64 * m, OUTF, (m == 0) ? 1 : 2);
            cudaEventRecord(eUpdR[m], s1);
        }
        cudaStreamWaitEvent(0, eXwG[xw_group_of(k)], 0);
        if (k >= 2) cudaStreamWaitEvent(0, eUpdR[k - 2], 0);
        seq_kernel<<<128, 256>>>(64 * k, w, u, out, Lout);
        if (k < NBLK - 1) cudaEventRecord(eSweep[k], 0);
    }

    for (int i = 0; i < 4; ++i) cudaEventDestroy(eXwG[i]);
    for (int i = 0; i < NBLK; ++i) {
        cudaEventDestroy(eSweep[i]);
        cudaEventDestroy(eUpdR[i]);
    }
    cudaEventDestroy(eRoot);
    cudaStreamDestroy(s1);
    cudaStreamDestroy(s2);
}